// round 6
// baseline (speedup 1.0000x reference)
#include <cuda_runtime.h>
#include <cuda_bf16.h>
#include <math.h>

// Problem dims: H=256, B=64, L=128, LABEL=128
// s = t*64 + b, S = 8192 sequential cells.

#define NSTEPS 8192
#define NCTA   32

// Scratch (device globals: allocation-free rule)
__device__ float              g_G [8192u * 1024u]; // 32 MB: input gates + bias
__device__ unsigned long long g_HF[8192u * 256u];  // 16 MB: {flag:hi32 | h:lo32}

// ---------------------------------------------------------------------------
// Morally-strong fused flag+value handshake (acquire/release b64: the PTX
// memory model guarantees atomicity — the R4 weak version could tear).
// ---------------------------------------------------------------------------
__device__ __forceinline__ unsigned long long poll_acq64(const unsigned long long* p) {
    unsigned long long v;
    do {
        asm volatile("ld.acquire.gpu.global.b64 %0, [%1];" : "=l"(v) : "l"(p) : "memory");
    } while ((v >> 32) == 0ull);
    return v;
}
__device__ __forceinline__ void st_rel64(unsigned long long* p, unsigned long long v) {
    asm volatile("st.release.gpu.global.b64 [%0], %1;" :: "l"(p), "l"(v) : "memory");
}

// ---------------------------------------------------------------------------
// Kernel A: G[s][j] = feats[s] . W_ih[j][0:1024] + b_ih[j] + b_hh[j]
// Tiled fp32 GEMM: M=8192, N=1024, K=1024.  (proven: 489us)
// ---------------------------------------------------------------------------
__global__ void __launch_bounds__(256) gemm_gx_kernel(
    const float* __restrict__ x, const float* __restrict__ hi,
    const float* __restrict__ W_ih,
    const float* __restrict__ b_ih, const float* __restrict__ b_hh)
{
    __shared__ float As[16][68];
    __shared__ float Bs[16][68];

    const int tid = threadIdx.x;
    const int bn  = blockIdx.x;
    const int bm  = blockIdx.y;
    const int tx  = tid & 15;
    const int ty  = tid >> 4;

    const int lm  = tid >> 2;
    const int lk4 = (tid & 3) * 4;

    const int s  = bm * 64 + lm;
    const int t  = s >> 6, b = s & 63;
    const float* xrow  = &x [((size_t)(b * 128 + t)) << 9];
    const float* hirow = &hi[((size_t)(b * 128 + t)) << 9];
    const float* wrow  = &W_ih[(size_t)(bn * 64 + (tid >> 2)) * 1280];

    float acc[4][4] = {};

    for (int kt = 0; kt < 64; kt++) {
        const int kbase = kt * 16 + lk4;
        float4 av;
        if (kbase < 512) av = *(const float4*)&xrow[kbase];
        else             av = *(const float4*)&hirow[kbase - 512];
        As[lk4 + 0][lm] = av.x;
        As[lk4 + 1][lm] = av.y;
        As[lk4 + 2][lm] = av.z;
        As[lk4 + 3][lm] = av.w;
        float4 bv = *(const float4*)&wrow[kbase];
        Bs[lk4 + 0][tid >> 2] = bv.x;
        Bs[lk4 + 1][tid >> 2] = bv.y;
        Bs[lk4 + 2][tid >> 2] = bv.z;
        Bs[lk4 + 3][tid >> 2] = bv.w;
        __syncthreads();

#pragma unroll
        for (int kk = 0; kk < 16; kk++) {
            float ar[4], br[4];
#pragma unroll
            for (int i = 0; i < 4; i++) ar[i] = As[kk][ty * 4 + i];
#pragma unroll
            for (int j = 0; j < 4; j++) br[j] = Bs[kk][tx * 4 + j];
#pragma unroll
            for (int i = 0; i < 4; i++)
#pragma unroll
                for (int j = 0; j < 4; j++)
                    acc[i][j] = fmaf(ar[i], br[j], acc[i][j]);
        }
        __syncthreads();
    }

    const int col0 = bn * 64 + tx * 4;
    float bias[4];
#pragma unroll
    for (int j = 0; j < 4; j++) bias[j] = b_ih[col0 + j] + b_hh[col0 + j];
#pragma unroll
    for (int i = 0; i < 4; i++) {
        const size_t row = (size_t)(bm * 64 + ty * 4 + i);
        float4 v;
        v.x = acc[i][0] + bias[0];
        v.y = acc[i][1] + bias[1];
        v.z = acc[i][2] + bias[2];
        v.w = acc[i][3] + bias[3];
        *(float4*)&g_G[row * 1024 + col0] = v;
    }
}

// ---------------------------------------------------------------------------
// Kernel B: sequential chain. 32 persistent CTAs x 256 threads.
// CTA k owns h indices k*8..k*8+7 (32 gate rows), weights register-resident.
// Handshake: single acquire/release b64 {flag|h} word per (step, h-index).
// out_prev = h[s-64] comes from a 64-step smem ring (no global traffic):
// thread tid writes each polled h[s-1][tid] into ring[(s-1)&63][tid]; the
// Phase-A read of ring[s&63] (= h[s-64]) is barrier-separated from all
// writers (slot rewritten only at step s+1, after this step's 2 barriers).
// cg>=8 threads consume only out_prev columns -> they run their 32 FMAs
// before polling; cg<8 run theirs after bar1. Bank rotation cc=(c+4*cg)&31
// keeps ring reads conflict-free.
// ---------------------------------------------------------------------------
__global__ void __launch_bounds__(256, 1) chain_kernel(
    const float* __restrict__ W_ih, const float* __restrict__ W_hh)
{
    extern __shared__ float ring[];   // 64 * 256 floats = 64 KB
    __shared__ float garr[32];
    __shared__ float csh[8];

    const int tid = threadIdx.x;
    const int k   = blockIdx.x;      // 0..31
    const int cg  = tid & 15;        // col group (32 cols each)
    const int rg  = tid >> 4;        // row group (2 rows each)

    const int r0 = rg * 2, r1 = r0 + 1;
    const int grow0 = (r0 >> 3) * 256 + k * 8 + (r0 & 7);
    const int grow1 = (r1 >> 3) * 256 + k * 8 + (r1 & 7);

    // Register-resident weights (proven layout):
    // ccol<256 -> W_hh col; ccol in [256,512) -> W_ih[:, 1024+ccol-256]
    float w0[32], w1[32];
#pragma unroll
    for (int c = 0; c < 32; c++) {
        const int ccol = cg * 32 + c;
        if (ccol < 256) {
            w0[c] = W_hh[(size_t)grow0 * 256 + ccol];
            w1[c] = W_hh[(size_t)grow1 * 256 + ccol];
        } else {
            w0[c] = W_ih[(size_t)grow0 * 1280 + 768 + ccol];
            w1[c] = W_ih[(size_t)grow1 * 1280 + 768 + ccol];
        }
    }

    if (tid < 8) csh[tid] = 0.f;
    __syncthreads();

    for (int s = 0; s < NSTEPS; s++) {
        // prefetch this step's G rows (independent of the wait)
        float gp0 = 0.f, gp1 = 0.f;
        if (cg == 0) {
            const size_t gb = (size_t)s * 1024;
            gp0 = __ldcg(&g_G[gb + grow0]);
            gp1 = __ldcg(&g_G[gb + grow1]);
        }

        float a0 = 0.f, a1 = 0.f;

        // ---- Phase A: out_prev FMAs straight from the smem ring (no wait)
        if (s >= 64 && cg >= 8) {
            const float* rb = &ring[(s & 63) * 256 + (cg - 8) * 32];
#pragma unroll
            for (int c = 0; c < 32; c++) {
                const int cc = (c + (cg - 8) * 4) & 31;   // bank rotation
                const float vv = rb[cc];
                a0 = fmaf(w0[cc], vv, a0);
                a1 = fmaf(w1[cc], vv, a1);
            }
        }

        // ---- Phase B: single-hop acquire poll of h[s-1][tid]
        float hv = 0.f;
        if (s > 0) {
            unsigned long long w = poll_acq64(&g_HF[(size_t)(s - 1) * 256 + tid]);
            hv = __uint_as_float((unsigned)w);
        }
        ring[((s - 1) & 63) * 256 + tid] = hv;
        __syncthreads();   // bar1

        if (s > 0 && cg < 8) {
            const float* rb = &ring[((s - 1) & 63) * 256 + cg * 32];
#pragma unroll
            for (int c = 0; c < 32; c++) {
                const int cc = (c + cg * 4) & 31;         // bank rotation
                const float vv = rb[cc];
                a0 = fmaf(w0[cc], vv, a0);
                a1 = fmaf(w1[cc], vv, a1);
            }
        }

        // reduce across the 16 col-groups (xor within 16-lane halves)
#pragma unroll
        for (int off = 1; off < 16; off <<= 1) {
            a0 += __shfl_xor_sync(0xffffffffu, a0, off);
            a1 += __shfl_xor_sync(0xffffffffu, a1, off);
        }
        if (cg == 0) {
            garr[r0] = a0 + gp0;
            garr[r1] = a1 + gp1;
        }
        __syncthreads();   // bar2

        // gates + state update + single release publish
        if (tid < 8) {
            const float gi = garr[tid];
            const float gf = garr[8 + tid];
            const float gg = garr[16 + tid];
            const float go = garr[24 + tid];
            const float iv = 1.f / (1.f + __expf(-gi));
            const float fv = 1.f / (1.f + __expf(-gf));
            const float gv = tanhf(gg);
            const float ovg = 1.f / (1.f + __expf(-go));
            const float cv = fv * csh[tid] + iv * gv;
            csh[tid] = cv;
            const float hvout = ovg * tanhf(cv);
            const unsigned long long pw =
                (1ull << 32) | (unsigned long long)__float_as_uint(hvout);
            st_rel64(&g_HF[(size_t)s * 256 + k * 8 + tid], pw);
        }
    }
}

// ---------------------------------------------------------------------------
// Kernel C: out[b][t][l] = H[s] . W_fc[l] + b_fc[l], s = t*64+b
// ---------------------------------------------------------------------------
__global__ void __launch_bounds__(128) fc_kernel(
    const float* __restrict__ W_fc, const float* __restrict__ b_fc,
    float* __restrict__ out)
{
    __shared__ float hrow[256];
    const int s = blockIdx.x;
    const int l = threadIdx.x;
    hrow[l]       = __uint_as_float((unsigned)g_HF[(size_t)s * 256 + l]);
    hrow[128 + l] = __uint_as_float((unsigned)g_HF[(size_t)s * 256 + 128 + l]);
    __syncthreads();

    float acc = b_fc[l];
    const float* wr = &W_fc[(size_t)l * 256];
#pragma unroll 8
    for (int j = 0; j < 256; j++) acc = fmaf(wr[j], hrow[j], acc);

    const int t = s >> 6, b = s & 63;
    out[((size_t)b << 14) + (size_t)t * 128 + l] = acc;
}

// ---------------------------------------------------------------------------
extern "C" void kernel_launch(void* const* d_in, const int* in_sizes, int n_in,
                              void* d_out, int out_size)
{
    const float* x    = (const float*)d_in[0];
    const float* hi   = (const float*)d_in[1];
    const float* W_ih = (const float*)d_in[2];
    const float* W_hh = (const float*)d_in[3];
    const float* b_ih = (const float*)d_in[4];
    const float* b_hh = (const float*)d_in[5];
    const float* W_fc = (const float*)d_in[6];
    const float* b_fc = (const float*)d_in[7];
    float* out = (float*)d_out;

    // clear {flag|h} words every call/replay
    void* hp = nullptr;
    cudaGetSymbolAddress(&hp, g_HF);
    cudaMemsetAsync(hp, 0, 8192u * 256u * sizeof(unsigned long long));

    const int ring_bytes = 64 * 256 * sizeof(float);   // 64 KB dynamic smem
    cudaFuncSetAttribute(chain_kernel,
                         cudaFuncAttributeMaxDynamicSharedMemorySize, ring_bytes);

    gemm_gx_kernel<<<dim3(16, 128), 256>>>(x, hi, W_ih, b_ih, b_hh);
    chain_kernel<<<NCTA, 256, ring_bytes>>>(W_ih, W_hh);
    fc_kernel<<<NSTEPS, 128>>>(W_fc, b_fc, out);
}

// round 7
// speedup vs baseline: 2.0605x; 2.0605x over previous
#include <cuda_runtime.h>
#include <cuda_bf16.h>
#include <math.h>

// Problem dims: H=256, B=64, L=128, LABEL=128
// s = t*64 + b, S = 8192 sequential cells.

#define NSTEPS 8192
#define NCTA   32
#define RSTRIDE 264          // ring slot stride: 8 groups * 33 padded floats
#define RING_FLOATS (64 * RSTRIDE)

// Scratch (device globals: allocation-free rule)
__device__ float              g_G [8192u * 1024u]; // 32 MB: input gates + bias
__device__ unsigned long long g_HF[8192u * 256u];  // 16 MB: {flag:hi32 | h:lo32}

// ---------------------------------------------------------------------------
// Fused flag+value handshake with RELAXED atomics: morally strong (no tearing,
// unlike weak .cg loads — the R4 bug) but fence-free (unlike acquire/release —
// the R5 overhead). All inter-CTA state is in this one 64-bit word, so no
// cross-address ordering is required.
// ---------------------------------------------------------------------------
__device__ __forceinline__ unsigned long long poll_rlx64(const unsigned long long* p) {
    unsigned long long v;
    do {
        asm volatile("ld.relaxed.gpu.global.b64 %0, [%1];" : "=l"(v) : "l"(p) : "memory");
    } while ((v >> 32) == 0ull);
    return v;
}
__device__ __forceinline__ void st_rlx64(unsigned long long* p, unsigned long long v) {
    asm volatile("st.relaxed.gpu.global.b64 [%0], %1;" :: "l"(p), "l"(v) : "memory");
}

__device__ __forceinline__ float fast_sigmoid(float x) {
    return __fdividef(1.f, 1.f + __expf(-x));
}
__device__ __forceinline__ float fast_tanh(float x) {
    // 1 - 2/(e^{2x}+1); correct limits at +/-inf via __expf saturation
    return 1.f - __fdividef(2.f, __expf(2.f * x) + 1.f);
}

// ---------------------------------------------------------------------------
// Kernel A: G[s][j] = feats[s] . W_ih[j][0:1024] + b_ih[j] + b_hh[j]
// Tiled fp32 GEMM: M=8192, N=1024, K=1024.  (proven: 489us)
// ---------------------------------------------------------------------------
__global__ void __launch_bounds__(256) gemm_gx_kernel(
    const float* __restrict__ x, const float* __restrict__ hi,
    const float* __restrict__ W_ih,
    const float* __restrict__ b_ih, const float* __restrict__ b_hh)
{
    __shared__ float As[16][68];
    __shared__ float Bs[16][68];

    const int tid = threadIdx.x;
    const int bn  = blockIdx.x;
    const int bm  = blockIdx.y;
    const int tx  = tid & 15;
    const int ty  = tid >> 4;

    const int lm  = tid >> 2;
    const int lk4 = (tid & 3) * 4;

    const int s  = bm * 64 + lm;
    const int t  = s >> 6, b = s & 63;
    const float* xrow  = &x [((size_t)(b * 128 + t)) << 9];
    const float* hirow = &hi[((size_t)(b * 128 + t)) << 9];
    const float* wrow  = &W_ih[(size_t)(bn * 64 + (tid >> 2)) * 1280];

    float acc[4][4] = {};

    for (int kt = 0; kt < 64; kt++) {
        const int kbase = kt * 16 + lk4;
        float4 av;
        if (kbase < 512) av = *(const float4*)&xrow[kbase];
        else             av = *(const float4*)&hirow[kbase - 512];
        As[lk4 + 0][lm] = av.x;
        As[lk4 + 1][lm] = av.y;
        As[lk4 + 2][lm] = av.z;
        As[lk4 + 3][lm] = av.w;
        float4 bv = *(const float4*)&wrow[kbase];
        Bs[lk4 + 0][tid >> 2] = bv.x;
        Bs[lk4 + 1][tid >> 2] = bv.y;
        Bs[lk4 + 2][tid >> 2] = bv.z;
        Bs[lk4 + 3][tid >> 2] = bv.w;
        __syncthreads();

#pragma unroll
        for (int kk = 0; kk < 16; kk++) {
            float ar[4], br[4];
#pragma unroll
            for (int i = 0; i < 4; i++) ar[i] = As[kk][ty * 4 + i];
#pragma unroll
            for (int j = 0; j < 4; j++) br[j] = Bs[kk][tx * 4 + j];
#pragma unroll
            for (int i = 0; i < 4; i++)
#pragma unroll
                for (int j = 0; j < 4; j++)
                    acc[i][j] = fmaf(ar[i], br[j], acc[i][j]);
        }
        __syncthreads();
    }

    const int col0 = bn * 64 + tx * 4;
    float bias[4];
#pragma unroll
    for (int j = 0; j < 4; j++) bias[j] = b_ih[col0 + j] + b_hh[col0 + j];
#pragma unroll
    for (int i = 0; i < 4; i++) {
        const size_t row = (size_t)(bm * 64 + ty * 4 + i);
        float4 v;
        v.x = acc[i][0] + bias[0];
        v.y = acc[i][1] + bias[1];
        v.z = acc[i][2] + bias[2];
        v.w = acc[i][3] + bias[3];
        *(float4*)&g_G[row * 1024 + col0] = v;
    }
}

// ---------------------------------------------------------------------------
// Kernel B: sequential chain. 32 persistent CTAs x 256 threads, 2 bars/step.
// CTA k owns h indices k*8..k*8+7 (32 gate rows). Weights register-resident
// with STATIC indexing (thread (rg,cg): rows 2rg,2rg+1; cols cg*32..+31 of
// the 512-col [h | out_prev] space — proven R1/R3 layout).
// All h values flow through a zero-initialized 64-slot smem ring:
//   fill(s): thread tid writes polled h[s-1][tid] into slot (s-1)&63.
//   compute(s): cg<8 lanes read slot (s-1)&63 (= h[s-1]); cg>=8 lanes read
//   slot s&63 (= h[s-64] = out_prev; zeros for s<64 via init). Same loop
//   body, different pointer base -> no divergence, no LMEM.
// Padded-33 groups + adjacent slots (stride 264 = 8 mod 32) => conflict-free.
// ---------------------------------------------------------------------------
__global__ void __launch_bounds__(256, 1) chain_kernel(
    const float* __restrict__ W_ih, const float* __restrict__ W_hh)
{
    extern __shared__ float ring[];   // 64 * 264 floats
    __shared__ float garr[32];

    const int tid = threadIdx.x;
    const int k   = blockIdx.x;      // 0..31
    const int cg  = tid & 15;        // col group (32 cols each)
    const int rg  = tid >> 4;        // row group (2 rows each)

    const int r0 = rg * 2, r1 = r0 + 1;
    const int grow0 = (r0 >> 3) * 256 + k * 8 + (r0 & 7);
    const int grow1 = (r1 >> 3) * 256 + k * 8 + (r1 & 7);

    // Register-resident weights, static indices (proven layout):
    // ccol<256 -> W_hh col; ccol in [256,512) -> W_ih[:, 1024+ccol-256]
    float w0[32], w1[32];
#pragma unroll
    for (int c = 0; c < 32; c++) {
        const int ccol = cg * 32 + c;
        if (ccol < 256) {
            w0[c] = W_hh[(size_t)grow0 * 256 + ccol];
            w1[c] = W_hh[(size_t)grow1 * 256 + ccol];
        } else {
            w0[c] = W_ih[(size_t)grow0 * 1280 + 768 + ccol];
            w1[c] = W_ih[(size_t)grow1 * 1280 + 768 + ccol];
        }
    }

    // zero-init the ring: makes out_prev reads for s<64 (and h at s=0) valid
    for (int i = tid; i < RING_FLOATS; i += 256) ring[i] = 0.f;

    float c_state = 0.f;                       // used by tid<8 only
    const int fill_off = (tid >> 5) * 33 + (tid & 31);
    const int coff     = (cg & 7) * 33;        // reader group offset
    const int slot_back = (cg < 8) ? 1 : 0;    // cg<8: h[s-1]; cg>=8: h[s-64]
    __syncthreads();

    for (int s = 0; s < NSTEPS; s++) {
        // prefetch this step's G rows (independent of the wait)
        float gp0 = 0.f, gp1 = 0.f;
        if (cg == 0) {
            const size_t gb = (size_t)s * 1024;
            gp0 = __ldcg(&g_G[gb + grow0]);
            gp1 = __ldcg(&g_G[gb + grow1]);
        }

        // fill: single-hop relaxed poll of the fused {flag|h} word
        float hv = 0.f;
        if (s > 0) {
            unsigned long long w = poll_rlx64(&g_HF[(size_t)(s - 1) * 256 + tid]);
            hv = __uint_as_float((unsigned)w);
        }
        ring[((s - 1) & 63) * RSTRIDE + fill_off] = hv;
        __syncthreads();   // bar1

        // matvec: uniform loop, per-lane pointer base selects h vs out_prev
        const float* src = &ring[((s - slot_back) & 63) * RSTRIDE + coff];
        float a0 = 0.f, a1 = 0.f;
#pragma unroll
        for (int c = 0; c < 32; c++) {
            const float vv = src[c];
            a0 = fmaf(w0[c], vv, a0);
            a1 = fmaf(w1[c], vv, a1);
        }
        // reduce across the 16 col-groups (xor stays within 16-lane halves)
#pragma unroll
        for (int off = 1; off < 16; off <<= 1) {
            a0 += __shfl_xor_sync(0xffffffffu, a0, off);
            a1 += __shfl_xor_sync(0xffffffffu, a1, off);
        }
        if (cg == 0) {
            garr[r0] = a0 + gp0;
            garr[r1] = a1 + gp1;
        }
        __syncthreads();   // bar2

        // gates + state update + single relaxed publish (8 producer threads)
        if (tid < 8) {
            const float gi = garr[tid];
            const float gf = garr[8 + tid];
            const float gg = garr[16 + tid];
            const float go = garr[24 + tid];
            const float iv = fast_sigmoid(gi);
            const float fv = fast_sigmoid(gf);
            const float gv = fast_tanh(gg);
            const float ov = fast_sigmoid(go);
            c_state = fv * c_state + iv * gv;
            const float hvout = ov * fast_tanh(c_state);
            const unsigned long long pw =
                (1ull << 32) | (unsigned long long)__float_as_uint(hvout);
            st_rlx64(&g_HF[(size_t)s * 256 + k * 8 + tid], pw);
        }
    }
}

// ---------------------------------------------------------------------------
// Kernel C: out[b][t][l] = H[s] . W_fc[l] + b_fc[l], s = t*64+b
// ---------------------------------------------------------------------------
__global__ void __launch_bounds__(128) fc_kernel(
    const float* __restrict__ W_fc, const float* __restrict__ b_fc,
    float* __restrict__ out)
{
    __shared__ float hrow[256];
    const int s = blockIdx.x;
    const int l = threadIdx.x;
    hrow[l]       = __uint_as_float((unsigned)g_HF[(size_t)s * 256 + l]);
    hrow[128 + l] = __uint_as_float((unsigned)g_HF[(size_t)s * 256 + 128 + l]);
    __syncthreads();

    float acc = b_fc[l];
    const float* wr = &W_fc[(size_t)l * 256];
#pragma unroll 8
    for (int j = 0; j < 256; j++) acc = fmaf(wr[j], hrow[j], acc);

    const int t = s >> 6, b = s & 63;
    out[((size_t)b << 14) + (size_t)t * 128 + l] = acc;
}

// ---------------------------------------------------------------------------
extern "C" void kernel_launch(void* const* d_in, const int* in_sizes, int n_in,
                              void* d_out, int out_size)
{
    const float* x    = (const float*)d_in[0];
    const float* hi   = (const float*)d_in[1];
    const float* W_ih = (const float*)d_in[2];
    const float* W_hh = (const float*)d_in[3];
    const float* b_ih = (const float*)d_in[4];
    const float* b_hh = (const float*)d_in[5];
    const float* W_fc = (const float*)d_in[6];
    const float* b_fc = (const float*)d_in[7];
    float* out = (float*)d_out;

    // clear {flag|h} words every call/replay
    void* hp = nullptr;
    cudaGetSymbolAddress(&hp, g_HF);
    cudaMemsetAsync(hp, 0, 8192u * 256u * sizeof(unsigned long long));

    const int ring_bytes = RING_FLOATS * sizeof(float);   // 67584 B
    cudaFuncSetAttribute(chain_kernel,
                         cudaFuncAttributeMaxDynamicSharedMemorySize, ring_bytes);

    gemm_gx_kernel<<<dim3(16, 128), 256>>>(x, hi, W_ih, b_ih, b_hh);
    chain_kernel<<<NCTA, 256, ring_bytes>>>(W_ih, W_hh);
    fc_kernel<<<NSTEPS, 128>>>(W_fc, b_fc, out);
}

// round 8
// speedup vs baseline: 2.0892x; 1.0139x over previous
#include <cuda_runtime.h>
#include <cuda_bf16.h>
#include <math.h>

// Problem dims: H=256, B=64, L=128, LABEL=128
// s = t*64 + b, S = 8192 sequential cells.

#define NSTEPS 8192
#define CHAIN_CTAS 32
#define GEMM_BLOCKS 2048
#define RSTRIDE 264                    // ring slot stride: 8 groups * 33 floats
#define RING_FLOATS (64 * RSTRIDE)    // 16896 floats = 67584 B dynamic smem

// Scratch (device globals: allocation-free rule)
__device__ float              g_G [8192u * 1024u]; // 32 MB: input gates + bias
__device__ unsigned long long g_HF[8192u * 256u];  // 16 MB: {flag:hi32 | h:lo32}
__device__ unsigned           g_gdone[128];        // per-M-tile completion counters

// ---------------------------------------------------------------------------
// handshake helpers
// ---------------------------------------------------------------------------
__device__ __forceinline__ void st_rlx64(unsigned long long* p, unsigned long long v) {
    asm volatile("st.relaxed.gpu.global.b64 [%0], %1;" :: "l"(p), "l"(v) : "memory");
}
// batched 4-deep relaxed poll: loads pipeline (LDG->LDG floor 4cyc), so after
// the first miss the re-check period is ~issue spacing, not full load latency.
__device__ __forceinline__ float poll_h(const unsigned long long* p) {
    unsigned long long v;
    for (;;) {
        unsigned long long a, b, c, d;
        asm volatile("ld.relaxed.gpu.global.b64 %0, [%1];" : "=l"(a) : "l"(p) : "memory");
        asm volatile("ld.relaxed.gpu.global.b64 %0, [%1];" : "=l"(b) : "l"(p) : "memory");
        asm volatile("ld.relaxed.gpu.global.b64 %0, [%1];" : "=l"(c) : "l"(p) : "memory");
        asm volatile("ld.relaxed.gpu.global.b64 %0, [%1];" : "=l"(d) : "l"(p) : "memory");
        if (a >> 32) { v = a; break; }
        if (b >> 32) { v = b; break; }
        if (c >> 32) { v = c; break; }
        if (d >> 32) { v = d; break; }
    }
    return __uint_as_float((unsigned)v);
}
__device__ __forceinline__ unsigned ld_acq32(const unsigned* p) {
    unsigned v;
    asm volatile("ld.acquire.gpu.global.b32 %0, [%1];" : "=r"(v) : "l"(p) : "memory");
    return v;
}
__device__ __forceinline__ float fast_sigmoid(float x) {
    return __fdividef(1.f, 1.f + __expf(-x));
}
__device__ __forceinline__ float fast_tanh(float x) {
    return 1.f - __fdividef(2.f, __expf(2.f * x) + 1.f);
}

// ---------------------------------------------------------------------------
// GEMM body (proven tile code): G[s][j] = feats[s].W_ih[j][0:1024] + bias[j]
// plus per-M-tile completion counter for the chain to gate on.
// ---------------------------------------------------------------------------
__device__ void gemm_body(
    float* smem, int gb,
    const float* __restrict__ x, const float* __restrict__ hi,
    const float* __restrict__ W_ih,
    const float* __restrict__ b_ih, const float* __restrict__ b_hh)
{
    float (*As)[68] = (float(*)[68])smem;
    float (*Bs)[68] = (float(*)[68])(smem + 16 * 68);

    const int tid = threadIdx.x;
    const int bn  = gb & 15;           // 0..15  (N tiles)
    const int bm  = gb >> 4;           // 0..127 (M tiles) -> completes in s-order
    const int tx  = tid & 15;
    const int ty  = tid >> 4;

    const int lm  = tid >> 2;
    const int lk4 = (tid & 3) * 4;

    const int s  = bm * 64 + lm;
    const int t  = s >> 6, b = s & 63;
    const float* xrow  = &x [((size_t)(b * 128 + t)) << 9];
    const float* hirow = &hi[((size_t)(b * 128 + t)) << 9];
    const float* wrow  = &W_ih[(size_t)(bn * 64 + (tid >> 2)) * 1280];

    float acc[4][4] = {};

    for (int kt = 0; kt < 64; kt++) {
        const int kbase = kt * 16 + lk4;
        float4 av;
        if (kbase < 512) av = *(const float4*)&xrow[kbase];
        else             av = *(const float4*)&hirow[kbase - 512];
        As[lk4 + 0][lm] = av.x;
        As[lk4 + 1][lm] = av.y;
        As[lk4 + 2][lm] = av.z;
        As[lk4 + 3][lm] = av.w;
        float4 bv = *(const float4*)&wrow[kbase];
        Bs[lk4 + 0][tid >> 2] = bv.x;
        Bs[lk4 + 1][tid >> 2] = bv.y;
        Bs[lk4 + 2][tid >> 2] = bv.z;
        Bs[lk4 + 3][tid >> 2] = bv.w;
        __syncthreads();

#pragma unroll
        for (int kk = 0; kk < 16; kk++) {
            float ar[4], br[4];
#pragma unroll
            for (int i = 0; i < 4; i++) ar[i] = As[kk][ty * 4 + i];
#pragma unroll
            for (int j = 0; j < 4; j++) br[j] = Bs[kk][tx * 4 + j];
#pragma unroll
            for (int i = 0; i < 4; i++)
#pragma unroll
                for (int j = 0; j < 4; j++)
                    acc[i][j] = fmaf(ar[i], br[j], acc[i][j]);
        }
        __syncthreads();
    }

    const int col0 = bn * 64 + tx * 4;
    float bias[4];
#pragma unroll
    for (int j = 0; j < 4; j++) bias[j] = b_ih[col0 + j] + b_hh[col0 + j];
#pragma unroll
    for (int i = 0; i < 4; i++) {
        const size_t row = (size_t)(bm * 64 + ty * 4 + i);
        float4 v;
        v.x = acc[i][0] + bias[0];
        v.y = acc[i][1] + bias[1];
        v.z = acc[i][2] + bias[2];
        v.w = acc[i][3] + bias[3];
        *(float4*)&g_G[row * 1024 + col0] = v;
    }

    // publish tile completion: stores -> fence -> join -> counter bump
    __threadfence();
    __syncthreads();
    if (tid == 0) atomicAdd(&g_gdone[bm], 1u);
}

// ---------------------------------------------------------------------------
// Chain body: CTA k (0..31), 8 warps. Warp j owns ALL FOUR gate rows of
// h-index jj=k*8+j. Lane (g2=lane>>4, cg=lane&15): rows {i,f} (g2=0) or
// {g,o} (g2=1); cols: cg<8 -> h cols cg*32..+31 (W_hh), cg>=8 -> out_prev
// cols (cg-8)*32..+31 (W_ih[:,1024+..]). 64 FMA/lane, weights in registers
// with static indexing. Reduction: 4 xor rounds over cg (sums h+out_prev
// halves), then shfl_xor 16 hands lane 0 all four gates -> gates computed
// in-warp, no garr, no second barrier. Publish = one relaxed b64 per warp.
// h values flow through a 64-slot smem ring; out_prev FMAs run before bar1
// (slot 63 steps old), hidden under the h[s-1] poll.
// ---------------------------------------------------------------------------
__device__ void chain_body(
    float* ring, int k,
    const float* __restrict__ W_ih, const float* __restrict__ W_hh)
{
    const int tid  = threadIdx.x;
    const int warp = tid >> 5;
    const int lane = tid & 31;
    const int g2   = lane >> 4;       // 0: rows {i,f}; 1: rows {g,o}
    const int cg   = lane & 15;       // col group

    const int jj = k * 8 + warp;            // h-index owned by this warp
    const int rA = (g2 ? 512 : 0) + jj;     // gate row A (i or g)
    const int rB = rA + 256;                // gate row B (f or o)

    // Register-resident weights, static indexing
    float wA[32], wB[32];
#pragma unroll
    for (int c = 0; c < 32; c++) {
        const int cc = (cg & 7) * 32 + c;   // 0..255 within the half
        if (cg < 8) {
            wA[c] = W_hh[(size_t)rA * 256 + cc];
            wB[c] = W_hh[(size_t)rB * 256 + cc];
        } else {
            wA[c] = W_ih[(size_t)rA * 1280 + 1024 + cc];
            wB[c] = W_ih[(size_t)rB * 1280 + 1024 + cc];
        }
    }

    // zero-init ring (covers out_prev for s<64 and h at s=0)
    for (int i = tid; i < RING_FLOATS; i += 256) ring[i] = 0.f;

    float c_state = 0.f;                          // live in lane 0 of each warp
    const int fill_off = (tid >> 5) * 33 + (tid & 31);
    __syncthreads();

    for (int s = 0; s < NSTEPS; s++) {
        // G readiness gate (once per 64 steps) + G prefetch (lane 0 per warp)
        float gi0 = 0.f, gf0 = 0.f, gg0 = 0.f, go0 = 0.f;
        if (lane == 0) {
            if ((s & 63) == 0) {
                while (ld_acq32(&g_gdone[s >> 6]) < 16u) { }
            }
            const size_t gb = (size_t)s * 1024 + jj;
            gi0 = __ldcg(&g_G[gb]);
            gf0 = __ldcg(&g_G[gb + 256]);
            gg0 = __ldcg(&g_G[gb + 512]);
            go0 = __ldcg(&g_G[gb + 768]);
        }

        float aA0 = 0.f, aA1 = 0.f, aB0 = 0.f, aB1 = 0.f;

        // out_prev FMAs BEFORE the poll/barrier (slot s&63 = h[s-64], 63 steps old)
        if (cg >= 8) {
            const float* src = &ring[(s & 63) * RSTRIDE + (cg - 8) * 33];
#pragma unroll
            for (int c = 0; c < 16; c++) {
                aA0 = fmaf(wA[c], src[c], aA0);
                aB0 = fmaf(wB[c], src[c], aB0);
            }
#pragma unroll
            for (int c = 16; c < 32; c++) {
                aA1 = fmaf(wA[c], src[c], aA1);
                aB1 = fmaf(wB[c], src[c], aB1);
            }
        }

        // fill: batched poll of h[s-1][tid], write into ring slot (s-1)&63
        float hv = 0.f;
        if (s > 0) hv = poll_h(&g_HF[(size_t)(s - 1) * 256 + tid]);
        ring[((s - 1) & 63) * RSTRIDE + fill_off] = hv;
        __syncthreads();   // the only barrier per step

        // h FMAs (the true dependency)
        if (cg < 8) {
            const float* src = &ring[((s - 1) & 63) * RSTRIDE + cg * 33];
#pragma unroll
            for (int c = 0; c < 16; c++) {
                aA0 = fmaf(wA[c], src[c], aA0);
                aB0 = fmaf(wB[c], src[c], aB0);
            }
#pragma unroll
            for (int c = 16; c < 32; c++) {
                aA1 = fmaf(wA[c], src[c], aA1);
                aB1 = fmaf(wB[c], src[c], aB1);
            }
        }

        float a0 = aA0 + aA1;   // row rA partial
        float a1 = aB0 + aB1;   // row rB partial
        // reduce over the 16 col groups (stays within each 16-lane half)
#pragma unroll
        for (int off = 1; off < 16; off <<= 1) {
            a0 += __shfl_xor_sync(0xffffffffu, a0, off);
            a1 += __shfl_xor_sync(0xffffffffu, a1, off);
        }
        // cross-half exchange: lane0 (g2=0) gets {g,o} sums from lane16
        const float b0 = __shfl_xor_sync(0xffffffffu, a0, 16);
        const float b1 = __shfl_xor_sync(0xffffffffu, a1, 16);

        if (lane == 0) {
            const float iv = fast_sigmoid(a0 + gi0);
            const float fv = fast_sigmoid(a1 + gf0);
            const float gv = fast_tanh  (b0 + gg0);
            const float ov = fast_sigmoid(b1 + go0);
            c_state = fv * c_state + iv * gv;
            const float hvout = ov * fast_tanh(c_state);
            const unsigned long long pw =
                (1ull << 32) | (unsigned long long)__float_as_uint(hvout);
            st_rlx64(&g_HF[(size_t)s * 256 + jj], pw);
        }
    }
}

// ---------------------------------------------------------------------------
// Fused kernel: blocks 0..31 = persistent chain CTAs (wave-1 resident),
// blocks 32..2079 = GEMM tiles (bm-major order -> tiles complete in s-order).
// ---------------------------------------------------------------------------
__global__ void __launch_bounds__(256) fused_kernel(
    const float* __restrict__ x, const float* __restrict__ hi,
    const float* __restrict__ W_ih, const float* __restrict__ W_hh,
    const float* __restrict__ b_ih, const float* __restrict__ b_hh)
{
    extern __shared__ float smem[];
    if (blockIdx.x < CHAIN_CTAS) {
        chain_body(smem, blockIdx.x, W_ih, W_hh);
    } else {
        gemm_body(smem, blockIdx.x - CHAIN_CTAS, x, hi, W_ih, b_ih, b_hh);
    }
}

// ---------------------------------------------------------------------------
// Kernel C: out[b][t][l] = H[s] . W_fc[l] + b_fc[l], s = t*64+b
// 8 steps per block: W_fc row read once per thread, reused x8.
// ---------------------------------------------------------------------------
__global__ void __launch_bounds__(128) fc_kernel(
    const float* __restrict__ W_fc, const float* __restrict__ b_fc,
    float* __restrict__ out)
{
    __shared__ float hrow[8][256];
    const int s0 = blockIdx.x * 8;
    const int l  = threadIdx.x;

#pragma unroll
    for (int ss = 0; ss < 8; ss++) {
        hrow[ss][l]       = __uint_as_float((unsigned)g_HF[(size_t)(s0 + ss) * 256 + l]);
        hrow[ss][128 + l] = __uint_as_float((unsigned)g_HF[(size_t)(s0 + ss) * 256 + 128 + l]);
    }
    __syncthreads();

    float acc[8];
    const float bias = b_fc[l];
#pragma unroll
    for (int ss = 0; ss < 8; ss++) acc[ss] = bias;

    const float* wr = &W_fc[(size_t)l * 256];
#pragma unroll 4
    for (int j = 0; j < 256; j++) {
        const float wv = wr[j];
#pragma unroll
        for (int ss = 0; ss < 8; ss++)
            acc[ss] = fmaf(wv, hrow[ss][j], acc[ss]);
    }

#pragma unroll
    for (int ss = 0; ss < 8; ss++) {
        const int s = s0 + ss;
        const int t = s >> 6, b = s & 63;
        out[((size_t)b << 14) + (size_t)t * 128 + l] = acc[ss];
    }
}

// ---------------------------------------------------------------------------
extern "C" void kernel_launch(void* const* d_in, const int* in_sizes, int n_in,
                              void* d_out, int out_size)
{
    const float* x    = (const float*)d_in[0];
    const float* hi   = (const float*)d_in[1];
    const float* W_ih = (const float*)d_in[2];
    const float* W_hh = (const float*)d_in[3];
    const float* b_ih = (const float*)d_in[4];
    const float* b_hh = (const float*)d_in[5];
    const float* W_fc = (const float*)d_in[6];
    const float* b_fc = (const float*)d_in[7];
    float* out = (float*)d_out;

    // clear {flag|h} words and tile counters every call/replay
    void* hp = nullptr;
    cudaGetSymbolAddress(&hp, g_HF);
    cudaMemsetAsync(hp, 0, 8192u * 256u * sizeof(unsigned long long));
    void* gp = nullptr;
    cudaGetSymbolAddress(&gp, g_gdone);
    cudaMemsetAsync(gp, 0, 128 * sizeof(unsigned));

    const int smem_bytes = RING_FLOATS * sizeof(float);   // 67584 B
    cudaFuncSetAttribute(fused_kernel,
                         cudaFuncAttributeMaxDynamicSharedMemorySize, smem_bytes);

    fused_kernel<<<CHAIN_CTAS + GEMM_BLOCKS, 256, smem_bytes>>>(
        x, hi, W_ih, W_hh, b_ih, b_hh);
    fc_kernel<<<NSTEPS / 8, 128>>>(W_fc, b_fc, out);
}

// round 9
// speedup vs baseline: 2.6281x; 1.2579x over previous
#include <cuda_runtime.h>
#include <cuda_bf16.h>
#include <math.h>

// Problem dims: H=256, B=64, L=128, LABEL=128
// s = t*64 + b, S = 8192 sequential cells.

#define NSTEPS 8192
#define CHAIN_CTAS 16            // one 16-CTA cluster (non-portable size)
#define GEMM_BLOCKS 2048
#define RSLOT 272                // ring slot: 8 groups * 34 floats (8B-aligned groups)
#define RING_FLOATS (64 * RSLOT) // 17408 floats = 69632 B dynamic smem
#define MAIL_DEPTH 4
#define MAIL_SLOT 264            // 8 groups * 33 u64 (bank-rotated)

// Scratch (device globals: allocation-free rule)
__device__ float    g_G[8192u * 1024u];  // 32 MB: input gates + bias
__device__ float    g_H[8192u * 256u];   // 8 MB: h history for fc
__device__ unsigned g_gdone[128];        // per-M-tile completion counters

// ---------------------------------------------------------------------------
// helpers
// ---------------------------------------------------------------------------
__device__ __forceinline__ unsigned ld_acq32(const unsigned* p) {
    unsigned v;
    asm volatile("ld.acquire.gpu.global.b32 %0, [%1];" : "=r"(v) : "l"(p) : "memory");
    return v;
}
__device__ __forceinline__ unsigned long long pk2(float lo, float hi) {
    unsigned long long r;
    asm("mov.b64 %0, {%1, %2};" : "=l"(r) : "f"(lo), "f"(hi));
    return r;
}
__device__ __forceinline__ void upk2(unsigned long long v, float& lo, float& hi) {
    asm("mov.b64 {%0, %1}, %2;" : "=f"(lo), "=f"(hi) : "l"(v));
}
__device__ __forceinline__ unsigned long long ffma2(
    unsigned long long a, unsigned long long b, unsigned long long c) {
    unsigned long long d;
    asm("fma.rn.f32x2 %0, %1, %2, %3;" : "=l"(d) : "l"(a), "l"(b), "l"(c));
    return d;
}
__device__ __forceinline__ unsigned smem_u32(const void* p) {
    unsigned a;
    asm("{ .reg .u64 t; cvta.to.shared.u64 t, %1; cvt.u32.u64 %0, t; }"
        : "=r"(a) : "l"(p));
    return a;
}
__device__ __forceinline__ unsigned mapa_rank(unsigned laddr, unsigned rank) {
    unsigned r;
    asm("mapa.shared::cluster.u32 %0, %1, %2;" : "=r"(r) : "r"(laddr), "r"(rank));
    return r;
}
// morally-strong cluster-scope DSMEM push / local poll (b64: no tearing)
__device__ __forceinline__ void st_clu64(unsigned addr, unsigned long long v) {
    asm volatile("st.relaxed.cluster.shared::cluster.b64 [%0], %1;"
                 :: "r"(addr), "l"(v) : "memory");
}
__device__ __forceinline__ unsigned long long ld_clu64(unsigned addr) {
    unsigned long long v;
    asm volatile("ld.relaxed.cluster.shared.b64 %0, [%1];" : "=l"(v) : "r"(addr) : "memory");
    return v;
}
__device__ __forceinline__ float fast_sigmoid(float x) {
    return __fdividef(1.f, 1.f + __expf(-x));
}
__device__ __forceinline__ float fast_tanh(float x) {
    return 1.f - __fdividef(2.f, __expf(2.f * x) + 1.f);
}

// ---------------------------------------------------------------------------
// GEMM body (proven tile code): G[s][j] = feats[s].W_ih[j][0:1024] + bias[j]
// ---------------------------------------------------------------------------
__device__ void gemm_body(
    float* smem, int gb,
    const float* __restrict__ x, const float* __restrict__ hi,
    const float* __restrict__ W_ih,
    const float* __restrict__ b_ih, const float* __restrict__ b_hh)
{
    float (*As)[68] = (float(*)[68])smem;
    float (*Bs)[68] = (float(*)[68])(smem + 16 * 68);

    const int tid = threadIdx.x;
    const int bn  = gb & 15;
    const int bm  = gb >> 4;           // M tiles complete in s-order
    const int tx  = tid & 15;
    const int ty  = tid >> 4;

    const int lm  = tid >> 2;
    const int lk4 = (tid & 3) * 4;

    const int s  = bm * 64 + lm;
    const int t  = s >> 6, b = s & 63;
    const float* xrow  = &x [((size_t)(b * 128 + t)) << 9];
    const float* hirow = &hi[((size_t)(b * 128 + t)) << 9];
    const float* wrow  = &W_ih[(size_t)(bn * 64 + (tid >> 2)) * 1280];

    float acc[4][4] = {};

    for (int kt = 0; kt < 64; kt++) {
        const int kbase = kt * 16 + lk4;
        float4 av;
        if (kbase < 512) av = *(const float4*)&xrow[kbase];
        else             av = *(const float4*)&hirow[kbase - 512];
        As[lk4 + 0][lm] = av.x;
        As[lk4 + 1][lm] = av.y;
        As[lk4 + 2][lm] = av.z;
        As[lk4 + 3][lm] = av.w;
        float4 bv = *(const float4*)&wrow[kbase];
        Bs[lk4 + 0][tid >> 2] = bv.x;
        Bs[lk4 + 1][tid >> 2] = bv.y;
        Bs[lk4 + 2][tid >> 2] = bv.z;
        Bs[lk4 + 3][tid >> 2] = bv.w;
        __syncthreads();

#pragma unroll
        for (int kk = 0; kk < 16; kk++) {
            float ar[4], br[4];
#pragma unroll
            for (int i = 0; i < 4; i++) ar[i] = As[kk][ty * 4 + i];
#pragma unroll
            for (int j = 0; j < 4; j++) br[j] = Bs[kk][tx * 4 + j];
#pragma unroll
            for (int i = 0; i < 4; i++)
#pragma unroll
                for (int j = 0; j < 4; j++)
                    acc[i][j] = fmaf(ar[i], br[j], acc[i][j]);
        }
        __syncthreads();
    }

    const int col0 = bn * 64 + tx * 4;
    float bias[4];
#pragma unroll
    for (int j = 0; j < 4; j++) bias[j] = b_ih[col0 + j] + b_hh[col0 + j];
#pragma unroll
    for (int i = 0; i < 4; i++) {
        const size_t row = (size_t)(bm * 64 + ty * 4 + i);
        float4 v;
        v.x = acc[i][0] + bias[0];
        v.y = acc[i][1] + bias[1];
        v.z = acc[i][2] + bias[2];
        v.w = acc[i][3] + bias[3];
        *(float4*)&g_G[row * 1024 + col0] = v;
    }

    __threadfence();
    __syncthreads();
    if (tid == 0) atomicAdd(&g_gdone[bm], 1u);
}

// ---------------------------------------------------------------------------
// Chain body: ONE cluster of 16 CTAs x 256 threads. CTA k owns h-indices
// k*16..k*16+15. Warp w: h-indices jj = k*16+2w+{0,1}; half-warp g2 = lane>>4
// owns all 4 gate rows of its jj. Lane cg = lane&15 owns h cols
// [16cg,16cg+16) AND out_prev cols [16cg,16cg+16): 64 FFMA2 + 16 LDS.64,
// out_prev half runs pre-barrier. Reduction stays in the half-warp; gates at
// lanes 0/16. Publish: {tag=s+1 | h} b64 pushed to all 16 CTAs' mailboxes
// (1 DSMEM store per lane); consumers poll LOCAL smem (tag-checked).
// h history for out_prev lives in a local 64-slot smem ring (as R7, proven
// barrier-ordering). Depth-4 mailbox slots are tag-checked -> reuse-safe.
// ---------------------------------------------------------------------------
__device__ void chain_body(
    float* ring, int k,
    const float* __restrict__ W_ih, const float* __restrict__ W_hh)
{
    __shared__ unsigned long long mail[MAIL_DEPTH * MAIL_SLOT];

    const int tid  = threadIdx.x;
    const int warp = tid >> 5;
    const int lane = tid & 31;
    const int g2   = lane >> 4;             // which of the warp's 2 h-indices
    const int cg   = lane & 15;             // 16-col group

    const int jj = k * 16 + 2 * warp + g2;  // owned h-index (gates side)

    // Register-resident packed weights: 4 gate rows x 16 cols, h + out_prev
    unsigned long long wh[4][8], wo[4][8];
#pragma unroll
    for (int r = 0; r < 4; r++) {
        const float* whrow = &W_hh[(size_t)(jj + 256 * r) * 256];
        const float* worow = &W_ih[(size_t)(jj + 256 * r) * 1280 + 1024];
#pragma unroll
        for (int c = 0; c < 8; c++) {
            const int col = cg * 16 + 2 * c;
            wh[r][c] = pk2(whrow[col], whrow[col + 1]);
            wo[r][c] = pk2(worow[col], worow[col + 1]);
        }
    }

    // init: zero ring (out_prev for s<64, h at s=0) and mailbox tags
    for (int i = tid; i < RING_FLOATS; i += 256) ring[i] = 0.f;
    for (int i = tid; i < MAIL_DEPTH * MAIL_SLOT; i += 256) mail[i] = 0ull;

    const unsigned mail_base = smem_u32(mail);
    const int ring_src_off = (cg >> 1) * 34 + (cg & 1) * 16;  // 8B-aligned
    const int fill_off     = (tid >> 5) * 34 + (tid & 31);
    const unsigned poll_off_base = (unsigned)((tid >> 5) * 33 + (tid & 31)) * 8u;

    float c_state = 0.f;   // meaningful at lanes 0,16

    __syncthreads();
    // cluster barrier: all 16 CTAs' mailboxes initialized before any push
    asm volatile("barrier.cluster.arrive.aligned;" ::: "memory");
    asm volatile("barrier.cluster.wait.aligned;" ::: "memory");

    for (int s = 0; s < NSTEPS; s++) {
        // G gating (once per 64 steps) + G prefetch (lanes 0,16 only)
        float gpre[4] = {0.f, 0.f, 0.f, 0.f};
        if (cg == 0) {
            if ((s & 63) == 0) {
                while (ld_acq32(&g_gdone[s >> 6]) < 16u) { }
            }
            const size_t gb = (size_t)s * 1024 + jj;
#pragma unroll
            for (int r = 0; r < 4; r++) gpre[r] = __ldcg(&g_G[gb + 256 * r]);
        }

        unsigned long long acc[4] = {0ull, 0ull, 0ull, 0ull};

        // ---- out_prev phase (pre-barrier; ring slot s&63 = h[s-64])
        {
            const unsigned long long* so =
                (const unsigned long long*)&ring[(s & 63) * RSLOT + ring_src_off];
#pragma unroll
            for (int c = 0; c < 8; c++) {
                const unsigned long long v = so[c];
#pragma unroll
                for (int r = 0; r < 4; r++) acc[r] = ffma2(wo[r][c], v, acc[r]);
            }
        }

        // ---- poll local mailbox for h[s-1][tid], fill ring
        float hv = 0.f;
        if (s > 0) {
            const unsigned pa = mail_base + (unsigned)(((s - 1) & (MAIL_DEPTH - 1))
                                 * MAIL_SLOT * 8) + poll_off_base;
            unsigned long long v;
            do { v = ld_clu64(pa); } while ((unsigned)(v >> 32) != (unsigned)s);
            hv = __uint_as_float((unsigned)v);
        }
        ring[((s - 1) & 63) * RSLOT + fill_off] = hv;
        __syncthreads();   // the only barrier per step

        // ---- h phase (the true dependency)
        {
            const unsigned long long* sh =
                (const unsigned long long*)&ring[((s - 1) & 63) * RSLOT + ring_src_off];
#pragma unroll
            for (int c = 0; c < 8; c++) {
                const unsigned long long v = sh[c];
#pragma unroll
                for (int r = 0; r < 4; r++) acc[r] = ffma2(wh[r][c], v, acc[r]);
            }
        }

        // reduce within the 16-lane half (4 gate sums)
        float g4[4];
#pragma unroll
        for (int r = 0; r < 4; r++) {
            float lo, hi2;
            upk2(acc[r], lo, hi2);
            g4[r] = lo + hi2;
        }
#pragma unroll
        for (int off = 1; off < 16; off <<= 1) {
#pragma unroll
            for (int r = 0; r < 4; r++)
                g4[r] += __shfl_xor_sync(0xffffffffu, g4[r], off);
        }

        // gates + publish
        unsigned long long pw = 0ull;
        if (cg == 0) {
            const float iv = fast_sigmoid(g4[0] + gpre[0]);
            const float fv = fast_sigmoid(g4[1] + gpre[1]);
            const float gv = fast_tanh  (g4[2] + gpre[2]);
            const float ov = fast_sigmoid(g4[3] + gpre[3]);
            c_state = fv * c_state + iv * gv;
            const float hvout = ov * fast_tanh(c_state);
            __stcg(&g_H[(size_t)s * 256 + jj], hvout);   // for fc (off-path)
            pw = ((unsigned long long)(unsigned)(s + 1) << 32)
               | (unsigned long long)__float_as_uint(hvout);
        }
        // broadcast the two publish words; every lane pushes one b64 to one CTA
        const unsigned long long p0 = __shfl_sync(0xffffffffu, pw, 0);
        const unsigned long long p1 = __shfl_sync(0xffffffffu, pw, 16);
        const unsigned long long pv = (lane < 16) ? p0 : p1;
        const int jpub = k * 16 + 2 * warp + g2;   // lane<16 -> g2=0's jj, etc.
        const unsigned la = mail_base
            + (unsigned)(((s & (MAIL_DEPTH - 1)) * MAIL_SLOT
                          + (jpub >> 5) * 33 + (jpub & 31)) * 8);
        st_clu64(mapa_rank(la, (unsigned)cg), pv);
    }

    // cluster barrier before exit: in-flight DSMEM pushes must land while
    // all peer CTAs (and their smem) are still alive
    asm volatile("barrier.cluster.arrive.aligned;" ::: "memory");
    asm volatile("barrier.cluster.wait.aligned;" ::: "memory");
}

// ---------------------------------------------------------------------------
// Fused kernel: blocks 0..15 = the chain cluster; 16..2063 = GEMM tiles.
// Launched with runtime cluster dim (16,1,1); GEMM clusters never sync.
// ---------------------------------------------------------------------------
__global__ void __launch_bounds__(256) fused_kernel(
    const float* __restrict__ x, const float* __restrict__ hi,
    const float* __restrict__ W_ih, const float* __restrict__ W_hh,
    const float* __restrict__ b_ih, const float* __restrict__ b_hh)
{
    extern __shared__ float smem[];
    if (blockIdx.x < CHAIN_CTAS) {
        chain_body(smem, blockIdx.x, W_ih, W_hh);
    } else {
        gemm_body(smem, blockIdx.x - CHAIN_CTAS, x, hi, W_ih, b_ih, b_hh);
    }
}

// ---------------------------------------------------------------------------
// Kernel C: out[b][t][l] = H[s] . W_fc[l] + b_fc[l], s = t*64+b
// ---------------------------------------------------------------------------
__global__ void __launch_bounds__(128) fc_kernel(
    const float* __restrict__ W_fc, const float* __restrict__ b_fc,
    float* __restrict__ out)
{
    __shared__ float hrow[8][256];
    const int s0 = blockIdx.x * 8;
    const int l  = threadIdx.x;

#pragma unroll
    for (int ss = 0; ss < 8; ss++) {
        hrow[ss][l]       = g_H[(size_t)(s0 + ss) * 256 + l];
        hrow[ss][128 + l] = g_H[(size_t)(s0 + ss) * 256 + 128 + l];
    }
    __syncthreads();

    float acc[8];
    const float bias = b_fc[l];
#pragma unroll
    for (int ss = 0; ss < 8; ss++) acc[ss] = bias;

    const float* wr = &W_fc[(size_t)l * 256];
#pragma unroll 4
    for (int j = 0; j < 256; j++) {
        const float wv = wr[j];
#pragma unroll
        for (int ss = 0; ss < 8; ss++)
            acc[ss] = fmaf(wv, hrow[ss][j], acc[ss]);
    }

#pragma unroll
    for (int ss = 0; ss < 8; ss++) {
        const int s = s0 + ss;
        const int t = s >> 6, b = s & 63;
        out[((size_t)b << 14) + (size_t)t * 128 + l] = acc[ss];
    }
}

// ---------------------------------------------------------------------------
extern "C" void kernel_launch(void* const* d_in, const int* in_sizes, int n_in,
                              void* d_out, int out_size)
{
    const float* x    = (const float*)d_in[0];
    const float* hi   = (const float*)d_in[1];
    const float* W_ih = (const float*)d_in[2];
    const float* W_hh = (const float*)d_in[3];
    const float* b_ih = (const float*)d_in[4];
    const float* b_hh = (const float*)d_in[5];
    const float* W_fc = (const float*)d_in[6];
    const float* b_fc = (const float*)d_in[7];
    float* out = (float*)d_out;

    // clear tile counters every call/replay (mailbox/ring cleared in-kernel)
    void* gp = nullptr;
    cudaGetSymbolAddress(&gp, g_gdone);
    cudaMemsetAsync(gp, 0, 128 * sizeof(unsigned));

    const int smem_bytes = RING_FLOATS * sizeof(float);   // 69632 B
    cudaFuncSetAttribute(fused_kernel,
                         cudaFuncAttributeMaxDynamicSharedMemorySize, smem_bytes);
    cudaFuncSetAttribute(fused_kernel,
                         cudaFuncAttributeNonPortableClusterSizeAllowed, 1);

    cudaLaunchConfig_t cfg = {};
    cfg.gridDim  = dim3(CHAIN_CTAS + GEMM_BLOCKS, 1, 1);  // 2064 = 129 * 16
    cfg.blockDim = dim3(256, 1, 1);
    cfg.dynamicSmemBytes = smem_bytes;
    cudaLaunchAttribute attrs[1];
    attrs[0].id = cudaLaunchAttributeClusterDimension;
    attrs[0].val.clusterDim.x = 16;
    attrs[0].val.clusterDim.y = 1;
    attrs[0].val.clusterDim.z = 1;
    cfg.attrs = attrs;
    cfg.numAttrs = 1;
    cudaLaunchKernelEx(&cfg, fused_kernel, x, hi, W_ih, W_hh, b_ih, b_hh);

    fc_kernel<<<NSTEPS / 8, 128>>>(W_fc, b_fc, out);
}

// round 10
// speedup vs baseline: 3.2264x; 1.2277x over previous
#include <cuda_runtime.h>
#include <cuda_bf16.h>
#include <math.h>

// Problem dims: H=256, B=64, L=128, LABEL=128
// s = t*64 + b, S = 8192 sequential cells.

#define NSTEPS 8192
#define CHAIN_CTAS 16             // one 16-CTA cluster (non-portable size)
#define GEMM_BLOCKS 2048
#define MAIL_DEPTH 67             // odd, >=65 => structurally reuse-safe
#define MAIL_SLOT 144             // u64 words/slot: 16 groups * 9 (8 pairs + 1 pad)

// Scratch (device globals: allocation-free rule)
__device__ float    g_G[8192u * 1024u];  // 32 MB: input gates + bias
__device__ float    g_H[8192u * 256u];   // 8 MB: exact h history for fc
__device__ unsigned g_gdone[128];        // per-M-tile completion counters

// ---------------------------------------------------------------------------
// helpers
// ---------------------------------------------------------------------------
__device__ __forceinline__ unsigned ld_acq32(const unsigned* p) {
    unsigned v;
    asm volatile("ld.acquire.gpu.global.b32 %0, [%1];" : "=r"(v) : "l"(p) : "memory");
    return v;
}
__device__ __forceinline__ unsigned long long pk2(float lo, float hi) {
    unsigned long long r;
    asm("mov.b64 %0, {%1, %2};" : "=l"(r) : "f"(lo), "f"(hi));
    return r;
}
__device__ __forceinline__ void upk2(unsigned long long v, float& lo, float& hi) {
    asm("mov.b64 {%0, %1}, %2;" : "=f"(lo), "=f"(hi) : "l"(v));
}
__device__ __forceinline__ unsigned long long ffma2(
    unsigned long long a, unsigned long long b, unsigned long long c) {
    unsigned long long d;
    asm("fma.rn.f32x2 %0, %1, %2, %3;" : "=l"(d) : "l"(a), "l"(b), "l"(c));
    return d;
}
__device__ __forceinline__ unsigned smem_u32(const void* p) {
    unsigned a;
    asm("{ .reg .u64 t; cvta.to.shared.u64 t, %1; cvt.u32.u64 %0, t; }"
        : "=r"(a) : "l"(p));
    return a;
}
__device__ __forceinline__ unsigned mapa_rank(unsigned laddr, unsigned rank) {
    unsigned r;
    asm("mapa.shared::cluster.u32 %0, %1, %2;" : "=r"(r) : "r"(laddr), "r"(rank));
    return r;
}
__device__ __forceinline__ void st_clu64(unsigned addr, unsigned long long v) {
    asm volatile("st.relaxed.cluster.shared::cluster.b64 [%0], %1;"
                 :: "r"(addr), "l"(v) : "memory");
}
__device__ __forceinline__ unsigned long long ld_clu64(unsigned addr) {
    unsigned long long v;
    asm volatile("ld.relaxed.cluster.shared.b64 %0, [%1];" : "=l"(v) : "r"(addr) : "memory");
    return v;
}
__device__ __forceinline__ float fast_sigmoid(float x) {
    return __fdividef(1.f, 1.f + __expf(-x));
}
__device__ __forceinline__ float fast_tanh(float x) {
    return 1.f - __fdividef(2.f, __expf(2.f * x) + 1.f);
}

// ---------------------------------------------------------------------------
// GEMM body (proven tile code): G[s][j] = feats[s].W_ih[j][0:1024] + bias[j]
// ---------------------------------------------------------------------------
__device__ void gemm_body(
    float* smem, int gb,
    const float* __restrict__ x, const float* __restrict__ hi,
    const float* __restrict__ W_ih,
    const float* __restrict__ b_ih, const float* __restrict__ b_hh)
{
    float (*As)[68] = (float(*)[68])smem;
    float (*Bs)[68] = (float(*)[68])(smem + 16 * 68);

    const int tid = threadIdx.x;
    const int bn  = gb & 15;
    const int bm  = gb >> 4;           // M tiles complete in s-order
    const int tx  = tid & 15;
    const int ty  = tid >> 4;

    const int lm  = tid >> 2;
    const int lk4 = (tid & 3) * 4;

    const int s  = bm * 64 + lm;
    const int t  = s >> 6, b = s & 63;
    const float* xrow  = &x [((size_t)(b * 128 + t)) << 9];
    const float* hirow = &hi[((size_t)(b * 128 + t)) << 9];
    const float* wrow  = &W_ih[(size_t)(bn * 64 + (tid >> 2)) * 1280];

    float acc[4][4] = {};

    for (int kt = 0; kt < 64; kt++) {
        const int kbase = kt * 16 + lk4;
        float4 av;
        if (kbase < 512) av = *(const float4*)&xrow[kbase];
        else             av = *(const float4*)&hirow[kbase - 512];
        As[lk4 + 0][lm] = av.x;
        As[lk4 + 1][lm] = av.y;
        As[lk4 + 2][lm] = av.z;
        As[lk4 + 3][lm] = av.w;
        float4 bv = *(const float4*)&wrow[kbase];
        Bs[lk4 + 0][tid >> 2] = bv.x;
        Bs[lk4 + 1][tid >> 2] = bv.y;
        Bs[lk4 + 2][tid >> 2] = bv.z;
        Bs[lk4 + 3][tid >> 2] = bv.w;
        __syncthreads();

#pragma unroll
        for (int kk = 0; kk < 16; kk++) {
            float ar[4], br[4];
#pragma unroll
            for (int i = 0; i < 4; i++) ar[i] = As[kk][ty * 4 + i];
#pragma unroll
            for (int j = 0; j < 4; j++) br[j] = Bs[kk][tx * 4 + j];
#pragma unroll
            for (int i = 0; i < 4; i++)
#pragma unroll
                for (int j = 0; j < 4; j++)
                    acc[i][j] = fmaf(ar[i], br[j], acc[i][j]);
        }
        __syncthreads();
    }

    const int col0 = bn * 64 + tx * 4;
    float bias[4];
#pragma unroll
    for (int j = 0; j < 4; j++) bias[j] = b_ih[col0 + j] + b_hh[col0 + j];
#pragma unroll
    for (int i = 0; i < 4; i++) {
        const size_t row = (size_t)(bm * 64 + ty * 4 + i);
        float4 v;
        v.x = acc[i][0] + bias[0];
        v.y = acc[i][1] + bias[1];
        v.z = acc[i][2] + bias[2];
        v.w = acc[i][3] + bias[3];
        *(float4*)&g_G[row * 1024 + col0] = v;
    }

    __threadfence();
    __syncthreads();
    if (tid == 0) atomicAdd(&g_gdone[bm], 1u);
}

// ---------------------------------------------------------------------------
// Chain body: ONE cluster of 16 CTAs x 256 threads; NO per-step barrier.
// CTA k owns h-indices 16k..16k+15; warp w owns jj = 16k+2w+g2 per half-warp
// (g2 = lane>>4). Lane cg = lane&15 handles cols [16cg,16cg+16) of BOTH h
// and out_prev: 64 FFMA2, weights register-resident packed.
// Mailbox word (pair p = j>>1) = {h[2p+1] | h[2p]} with bits[1:0] of the lo
// float replaced by the step stamp s&3 (perturbation ~2^-22, budget 1e-3).
// Consumer polls its 8 words for h[s-1] (stamp check) and reads h[s-64]
// stamp-free from the old slot (reuse-safety: a slot is overwritten only at
// s+3, which transitively requires OUR publish of s+2 — impossible at step s).
// After the butterfly reduce ALL 16 lanes hold the gate sums -> gates are
// computed redundantly (SIMT-free), c_state replicated, one shfl pairs the
// halves, lanes 0..15 push the packed word to the 16 CTAs.
// ---------------------------------------------------------------------------
__device__ void chain_body(
    unsigned long long* mail, int k,
    const float* __restrict__ W_ih, const float* __restrict__ W_hh)
{
    const int tid  = threadIdx.x;
    const int warp = tid >> 5;
    const int lane = tid & 31;
    const int g2   = lane >> 4;             // which of the warp's 2 h-indices
    const int cg   = lane & 15;             // 16-col group

    const int jj = k * 16 + 2 * warp + g2;  // owned h-index

    // Register-resident packed weights: 4 gate rows x 8 col-pairs, h + out_prev
    unsigned long long wh[4][8], wo[4][8];
#pragma unroll
    for (int r = 0; r < 4; r++) {
        const float* whrow = &W_hh[(size_t)(jj + 256 * r) * 256];
        const float* worow = &W_ih[(size_t)(jj + 256 * r) * 1280 + 1024];
#pragma unroll
        for (int c = 0; c < 8; c++) {
            const int col = cg * 16 + 2 * c;
            wh[r][c] = pk2(whrow[col], whrow[col + 1]);
            wo[r][c] = pk2(worow[col], worow[col + 1]);
        }
    }

    // init mailbox: slot x gets stamp (x&3)^1 (never matches its first writer)
    for (int x = 0; x < MAIL_DEPTH; x++) {
        const unsigned long long iw = (unsigned long long)((x & 3) ^ 1);
        for (int i = tid; i < MAIL_SLOT; i += 256) mail[x * MAIL_SLOT + i] = iw;
    }

    const unsigned mail_base = smem_u32(mail);
    const unsigned rd_off    = (unsigned)(9 * cg) * 8u;          // my 8-pair group
    const unsigned push_off  = (unsigned)(9 * k + warp) * 8u;    // my pair word

    float c_state = 0.f;   // replicated per lane (bit-identical by construction)

    __syncthreads();
    // cluster barrier: all mailboxes initialized before any push
    asm volatile("barrier.cluster.arrive.aligned;" ::: "memory");
    asm volatile("barrier.cluster.wait.aligned;" ::: "memory");

    int m = 0;  // s % 67
    for (int s = 0; s < NSTEPS; s++) {
        // G gating (once per 64 steps) + G prefetch (all lanes; 2 addrs/warp)
        if ((s & 63) == 0) {
            while (ld_acq32(&g_gdone[s >> 6]) < 16u) { }
        }
        float gpre[4];
        {
            const size_t gb = (size_t)s * 1024 + jj;
#pragma unroll
            for (int r = 0; r < 4; r++) gpre[r] = __ldcg(&g_G[gb + 256 * r]);
        }

        unsigned long long acc[4] = {0ull, 0ull, 0ull, 0ull};

        // ---- out_prev phase: read h[s-64] pairs straight from the old slot
        if (s >= 64) {
            const int o_slot = (m + 3 >= MAIL_DEPTH) ? m + 3 - MAIL_DEPTH : m + 3;
            const unsigned oa = mail_base + (unsigned)(o_slot * MAIL_SLOT) * 8u + rd_off;
#pragma unroll
            for (int c = 0; c < 8; c++) {
                const unsigned long long v = ld_clu64(oa + c * 8);
#pragma unroll
                for (int r = 0; r < 4; r++) acc[r] = ffma2(wo[r][c], v, acc[r]);
            }
        }

        // ---- poll h[s-1]: 8 stamp-checked words, then FFMA2 on raw words
        if (s > 0) {
            const int h_slot = (m == 0) ? MAIL_DEPTH - 1 : m - 1;
            const unsigned ha = mail_base + (unsigned)(h_slot * MAIL_SLOT) * 8u + rd_off;
            const unsigned stamp = (unsigned)((s - 1) & 3);
            unsigned long long v[8];
            for (;;) {
                bool ok = true;
#pragma unroll
                for (int c = 0; c < 8; c++) {
                    v[c] = ld_clu64(ha + c * 8);
                    ok &= (((unsigned)v[c] & 3u) == stamp);
                }
                if (ok) break;
            }
#pragma unroll
            for (int c = 0; c < 8; c++) {
#pragma unroll
                for (int r = 0; r < 4; r++) acc[r] = ffma2(wh[r][c], v[c], acc[r]);
            }
        }

        // butterfly reduce over the 16 col-groups: ALL lanes get the sums
        float g4[4];
#pragma unroll
        for (int r = 0; r < 4; r++) {
            float lo, hi2;
            upk2(acc[r], lo, hi2);
            g4[r] = lo + hi2;
        }
#pragma unroll
        for (int off = 1; off < 16; off <<= 1) {
#pragma unroll
            for (int r = 0; r < 4; r++)
                g4[r] += __shfl_xor_sync(0xffffffffu, g4[r], off);
        }

        // gates: redundant across the half-warp (SIMT-free), c_state replicated
        const float iv = fast_sigmoid(g4[0] + gpre[0]);
        const float fv = fast_sigmoid(g4[1] + gpre[1]);
        const float gv = fast_tanh  (g4[2] + gpre[2]);
        const float ov = fast_sigmoid(g4[3] + gpre[3]);
        c_state = fv * c_state + iv * gv;
        const float hv = ov * fast_tanh(c_state);

        // exact mirror for fc (off the critical path)
        if (cg == 0) __stcg(&g_H[(size_t)s * 256 + jj], hv);

        // pair the halves and push: lanes 0..15 -> 16 cluster CTAs
        const float partner = __shfl_xor_sync(0xffffffffu, hv, 16);
        if (lane < 16) {
            unsigned long long pw = pk2(hv, partner);            // {h1 | h0}
            pw = (pw & ~3ull) | (unsigned long long)(s & 3);     // stamp in h0 LSBs
            const unsigned la = mail_base + (unsigned)(m * MAIL_SLOT) * 8u + push_off;
            st_clu64(mapa_rank(la, (unsigned)lane), pw);
        }

        m = (m + 1 == MAIL_DEPTH) ? 0 : m + 1;
    }

    // cluster barrier before exit: peers' smem must outlive in-flight pushes
    asm volatile("barrier.cluster.arrive.aligned;" ::: "memory");
    asm volatile("barrier.cluster.wait.aligned;" ::: "memory");
}

// ---------------------------------------------------------------------------
// Fused kernel: blocks 0..15 = the chain cluster; 16..2063 = GEMM tiles.
// ---------------------------------------------------------------------------
__global__ void __launch_bounds__(256) fused_kernel(
    const float* __restrict__ x, const float* __restrict__ hi,
    const float* __restrict__ W_ih, const float* __restrict__ W_hh,
    const float* __restrict__ b_ih, const float* __restrict__ b_hh)
{
    extern __shared__ unsigned long long dynsmem[];
    if (blockIdx.x < CHAIN_CTAS) {
        chain_body(dynsmem, blockIdx.x, W_ih, W_hh);
    } else {
        gemm_body((float*)dynsmem, blockIdx.x - CHAIN_CTAS, x, hi, W_ih, b_ih, b_hh);
    }
}

// ---------------------------------------------------------------------------
// Kernel C: out[b][t][l] = H[s] . W_fc[l] + b_fc[l], s = t*64+b
// ---------------------------------------------------------------------------
__global__ void __launch_bounds__(128) fc_kernel(
    const float* __restrict__ W_fc, const float* __restrict__ b_fc,
    float* __restrict__ out)
{
    __shared__ float hrow[8][256];
    const int s0 = blockIdx.x * 8;
    const int l  = threadIdx.x;

#pragma unroll
    for (int ss = 0; ss < 8; ss++) {
        hrow[ss][l]       = g_H[(size_t)(s0 + ss) * 256 + l];
        hrow[ss][128 + l] = g_H[(size_t)(s0 + ss) * 256 + 128 + l];
    }
    __syncthreads();

    float acc[8];
    const float bias = b_fc[l];
#pragma unroll
    for (int ss = 0; ss < 8; ss++) acc[ss] = bias;

    const float* wr = &W_fc[(size_t)l * 256];
#pragma unroll 4
    for (int j = 0; j < 256; j++) {
        const float wv = wr[j];
#pragma unroll
        for (int ss = 0; ss < 8; ss++)
            acc[ss] = fmaf(wv, hrow[ss][j], acc[ss]);
    }

#pragma unroll
    for (int ss = 0; ss < 8; ss++) {
        const int s = s0 + ss;
        const int t = s >> 6, b = s & 63;
        out[((size_t)b << 14) + (size_t)t * 128 + l] = acc[ss];
    }
}

// ---------------------------------------------------------------------------
extern "C" void kernel_launch(void* const* d_in, const int* in_sizes, int n_in,
                              void* d_out, int out_size)
{
    const float* x    = (const float*)d_in[0];
    const float* hi   = (const float*)d_in[1];
    const float* W_ih = (const float*)d_in[2];
    const float* W_hh = (const float*)d_in[3];
    const float* b_ih = (const float*)d_in[4];
    const float* b_hh = (const float*)d_in[5];
    const float* W_fc = (const float*)d_in[6];
    const float* b_fc = (const float*)d_in[7];
    float* out = (float*)d_out;

    // clear tile counters every call/replay (mailbox init is in-kernel)
    void* gp = nullptr;
    cudaGetSymbolAddress(&gp, g_gdone);
    cudaMemsetAsync(gp, 0, 128 * sizeof(unsigned));

    const int smem_bytes = MAIL_DEPTH * MAIL_SLOT * sizeof(unsigned long long); // 77184
    cudaFuncSetAttribute(fused_kernel,
                         cudaFuncAttributeMaxDynamicSharedMemorySize, smem_bytes);
    cudaFuncSetAttribute(fused_kernel,
                         cudaFuncAttributeNonPortableClusterSizeAllowed, 1);

    cudaLaunchConfig_t cfg = {};
    cfg.gridDim  = dim3(CHAIN_CTAS + GEMM_BLOCKS, 1, 1);  // 2064 = 129 * 16
    cfg.blockDim = dim3(256, 1, 1);
    cfg.dynamicSmemBytes = smem_bytes;
    cudaLaunchAttribute attrs[1];
    attrs[0].id = cudaLaunchAttributeClusterDimension;
    attrs[0].val.clusterDim.x = 16;
    attrs[0].val.clusterDim.y = 1;
    attrs[0].val.clusterDim.z = 1;
    cfg.attrs = attrs;
    cfg.numAttrs = 1;
    cudaLaunchKernelEx(&cfg, fused_kernel, x, hi, W_ih, W_hh, b_ih, b_hh);

    fc_kernel<<<NSTEPS / 8, 128>>>(W_fc, b_fc, out);
}